// round 5
// baseline (speedup 1.0000x reference)
#include <cuda_runtime.h>
#include <cuda_bf16.h>
#include <cstdint>
#include <math.h>

// ---------------------------------------------------------------------------
// MultiHeadAttention (B=8, T=1024, E=768, H=12)
// Primary: split-bf16 tcgen05 pipeline (3 bf16 MMAs per fp32 GEMM).
// Safety:  proven fp32 SIMT pipeline runs after, guarded by g_ok (no-op if the
//          TC path produced valid data). Deterministic, graph-capturable.
// ---------------------------------------------------------------------------

#if defined(__CUDA_ARCH__) && (defined(__CUDA_ARCH_FEAT_SM103_ALL) || defined(__CUDA_ARCH_SPECIFIC__))
#define HAS_TC 1
#else
#define HAS_TC 0
#endif

#define SWZ(x) ((x) ^ (((x) >> 3) & 0x70))

// ------------------------- scratch (device globals) ------------------------
#define AL __align__(256)
__device__ AL __nv_bfloat16 g_xhi[8192 * 768];
__device__ AL __nv_bfloat16 g_xlo[8192 * 768];
__device__ AL __nv_bfloat16 g_WQth[12 * 768 * 768], g_WQtl[12 * 768 * 768];
__device__ AL __nv_bfloat16 g_WKth[12 * 768 * 768], g_WKtl[12 * 768 * 768];
__device__ AL __nv_bfloat16 g_WVth[12 * 768 * 768], g_WVtl[12 * 768 * 768];
__device__ AL __nv_bfloat16 g_WOth[768 * 9216], g_WOtl[768 * 9216];
__device__ AL __nv_bfloat16 g_Qhi[96 * 786432], g_Qlo[96 * 786432];
__device__ AL __nv_bfloat16 g_Khi[96 * 786432], g_Klo[96 * 786432];
__device__ AL __nv_bfloat16 g_Kthi[96 * 786432], g_Ktlo[96 * 786432];
__device__ AL __nv_bfloat16 g_Vhi[96 * 786432], g_Vlo[96 * 786432];
__device__ AL __nv_bfloat16 g_Vthi[96 * 786432], g_Vtlo[96 * 786432];
__device__ AL float         g_S[96 * 1048576];
__device__ AL __nv_bfloat16 g_Phi[96 * 1048576], g_Plo[96 * 1048576];
__device__ AL __nv_bfloat16 g_Zhi[96 * 786432], g_Zlo[96 * 786432];
// SIMT-fallback scratch
__device__ AL float g_Qf[96 * 786432];
__device__ AL float g_Kf[96 * 786432];
__device__ AL float g_Vf[96 * 786432];
__device__ AL float g_Zf[96 * 786432];
__device__ int g_ok;

// ------------------------------ PTX helpers --------------------------------
__device__ __forceinline__ uint32_t smem_u32(const void* p) {
    uint32_t a;
    asm("{ .reg .u64 t; cvta.to.shared.u64 t, %1; cvt.u32.u64 %0, t; }" : "=r"(a) : "l"(p));
    return a;
}
__device__ __forceinline__ uint64_t cvta_g(const void* p) {
    uint64_t r;
    asm("cvta.to.global.u64 %0, %1;" : "=l"(r) : "l"(p));
    return r;
}
__device__ __forceinline__ uint32_t elect_one_pred() {
    uint32_t pred;
    asm volatile(
        "{\n\t.reg .pred p;\n\telect.sync _|p, 0xFFFFFFFF;\n\t"
        "selp.b32 %0, 1, 0, p;\n\t}"
        : "=r"(pred));
    return pred;
}
__device__ __forceinline__ void mbar_init(uint32_t m, uint32_t cnt) {
    asm volatile("mbarrier.init.shared.b64 [%0], %1;" :: "r"(m), "r"(cnt) : "memory");
}
__device__ __forceinline__ void mbar_wait(uint32_t m, uint32_t ph) {
    asm volatile(
        "{\n\t.reg .pred P1;\n\t"
        "LAB_W%=:\n\t"
        "mbarrier.try_wait.parity.acquire.cta.shared::cta.b64 P1, [%0], %1, 0x989680;\n\t"
        "@P1 bra.uni LAB_D%=;\n\t"
        "bra.uni LAB_W%=;\n\t"
        "LAB_D%=:\n\t}"
        :: "r"(m), "r"(ph) : "memory");
}
#define CP_COMMIT() asm volatile("cp.async.commit_group;" ::: "memory")
#define CP_WAIT(n)  asm volatile("cp.async.wait_group %0;" :: "n"(n) : "memory")

// SW128 SMEM descriptor: layout 2, version 1, SBO=64, LBO=1
__device__ __forceinline__ uint64_t mk_desc(uint32_t addr) {
    return ((uint64_t)2 << 61) | ((uint64_t)1 << 46) | ((uint64_t)64 << 32) |
           ((uint64_t)1 << 16) | ((uint64_t)(addr >> 4) & 0x3FFF);
}

// idesc: dtype=F32(bit4), a=BF16(bit7), b=BF16(bit10), N=128(16<<17), M=128(8<<24)
#define IDESC 0x08200490u

#if HAS_TC
__device__ __forceinline__ void mma4(uint32_t d, uint64_t da, uint64_t db, bool first) {
#pragma unroll
    for (int ks = 0; ks < 4; ks++) {
        uint32_t en = (first && ks == 0) ? 0u : 1u;
        asm volatile(
            "{\n\t.reg .pred p;\n\tsetp.ne.u32 p, %4, 0;\n\t"
            "tcgen05.mma.cta_group::1.kind::f16 [%0], %1, %2, %3, {%5,%5,%5,%5}, p;\n\t}"
            :: "r"(d), "l"(da + ks * 2), "l"(db + ks * 2), "r"(IDESC), "r"(en), "r"(0u)
            : "memory");
    }
}

#define TCG_LD32(r, a)                                                          \
    asm volatile(                                                               \
        "tcgen05.ld.sync.aligned.32x32b.x32.b32 "                               \
        "{%0, %1, %2, %3, %4, %5, %6, %7, "                                     \
        " %8, %9, %10, %11, %12, %13, %14, %15, "                               \
        " %16, %17, %18, %19, %20, %21, %22, %23, "                             \
        " %24, %25, %26, %27, %28, %29, %30, %31}, [%32];"                      \
        : "=r"((r)[0]), "=r"((r)[1]), "=r"((r)[2]), "=r"((r)[3]),               \
          "=r"((r)[4]), "=r"((r)[5]), "=r"((r)[6]), "=r"((r)[7]),               \
          "=r"((r)[8]), "=r"((r)[9]), "=r"((r)[10]), "=r"((r)[11]),             \
          "=r"((r)[12]), "=r"((r)[13]), "=r"((r)[14]), "=r"((r)[15]),           \
          "=r"((r)[16]), "=r"((r)[17]), "=r"((r)[18]), "=r"((r)[19]),           \
          "=r"((r)[20]), "=r"((r)[21]), "=r"((r)[22]), "=r"((r)[23]),           \
          "=r"((r)[24]), "=r"((r)[25]), "=r"((r)[26]), "=r"((r)[27]),           \
          "=r"((r)[28]), "=r"((r)[29]), "=r"((r)[30]), "=r"((r)[31])            \
        : "r"(a))
#endif  // HAS_TC

// -------------------------- tile loader (cp.async) -------------------------
__device__ __forceinline__ void load_chunk(
    uint32_t buf, const __nv_bfloat16* ah, const __nv_bfloat16* al,
    const __nv_bfloat16* bh, const __nv_bfloat16* bl,
    long lda, long ldb, int k0, int tid)
{
    const __nv_bfloat16* srcs[4] = {ah, al, bh, bl};
    const long lds[4] = {lda, lda, ldb, ldb};
    const int cv = (tid & 7);
    const int rb = tid >> 3;
#pragma unroll
    for (int i = 0; i < 32; i++) {
        const int s = i >> 3;
        const int r = rb + (i & 7) * 16;
        const __nv_bfloat16* g = srcs[s] + (long)r * lds[s] + k0 + cv * 8;
        uint32_t d = buf + s * 16384 + SWZ(r * 128 + cv * 16);
        asm volatile("cp.async.cg.shared.global [%0], [%1], 16;"
                     :: "r"(d), "l"(cvta_g(g)) : "memory");
    }
}

// ------------------------------- TC GEMM kernel ----------------------------
__global__ __launch_bounds__(128, 1) __cluster_dims__(1, 1, 1)
void tc_gemm(int mode, float* __restrict__ out)
{
    extern __shared__ char smem[];
    const uint32_t sb = smem_u32(smem);
    const uint32_t MB0 = sb + 8, MB1 = sb + 16;
    const uint32_t BUF = (sb + 1024 + 1023) & ~1023u;   // 1024B-aligned tiles
    const int tid = threadIdx.x;

    const __nv_bfloat16 *Ah, *Al, *Bh, *Bl;
    __nv_bfloat16 *Ch = nullptr, *Cl = nullptr;
    float* Cf = nullptr;
    long lda, ldb, ldc;
    int K;
    const int z = blockIdx.z;

    if (mode == 0) {
        int which = z / 12, h = z - which * 12;
        Ah = g_xhi; Al = g_xlo; lda = 768; K = 768;
        if (which == 0)      { Bh = g_WQth; Bl = g_WQtl; Ch = g_Qhi; Cl = g_Qlo; }
        else if (which == 1) { Bh = g_WKth; Bl = g_WKtl; Ch = g_Khi; Cl = g_Klo; }
        else                 { Bh = g_WVth; Bl = g_WVtl; Ch = g_Vhi; Cl = g_Vlo; }
        Bh += (long)h * 589824;  Bl += (long)h * 589824;  ldb = 768;
        Ch += (long)h * 6291456; Cl += (long)h * 6291456; ldc = 768;
    } else if (mode == 1) {
        Ah = g_Qhi  + (long)z * 786432; Al = g_Qlo  + (long)z * 786432; lda = 768; K = 768;
        Bh = g_Kthi + (long)z * 786432; Bl = g_Ktlo + (long)z * 786432; ldb = 768;
        Cf = g_S + (long)z * 1048576; ldc = 1024;
    } else if (mode == 2) {
        Ah = g_Phi  + (long)z * 1048576; Al = g_Plo  + (long)z * 1048576; lda = 1024; K = 1024;
        Bh = g_Vthi + (long)z * 786432;  Bl = g_Vtlo + (long)z * 786432;  ldb = 1024;
        int h = z >> 3, b = z & 7;
        Ch = g_Zhi + (long)(b * 12 + h) * 786432;
        Cl = g_Zlo + (long)(b * 12 + h) * 786432; ldc = 768;
    } else {
        Ah = g_Zhi; Al = g_Zlo; lda = 9216; K = 9216;
        Bh = g_WOth; Bl = g_WOtl; ldb = 9216;
        Cf = out; ldc = 768;
    }
    const bool split = (Ch != nullptr);

    const long row0 = (long)blockIdx.y * 128;
    const long col0 = (long)blockIdx.x * 128;
    Ah += row0 * lda; Al += row0 * lda;
    Bh += col0 * ldb; Bl += col0 * ldb;

#if HAS_TC
    if (tid == 0) { mbar_init(MB0, 1); mbar_init(MB1, 1); }
    if (tid < 32) {
        asm volatile("tcgen05.alloc.cta_group::1.sync.aligned.shared::cta.b32 [%0], %1;"
                     :: "r"(sb), "r"(128u) : "memory");
    }
    __syncthreads();
    uint32_t tmem;
    asm volatile("ld.shared.b32 %0, [%1];" : "=r"(tmem) : "r"(sb));

    const int nc = K >> 6;

    load_chunk(BUF, Ah, Al, Bh, Bl, lda, ldb, 0, tid);
    CP_COMMIT();

    for (int c = 0; c < nc; c++) {
        const int cur = c & 1;
        if (c + 1 < nc) {
            const int nb = cur ^ 1;
            if (c >= 1) mbar_wait(nb ? MB1 : MB0, ((c - 1) >> 1) & 1);
            load_chunk(BUF + nb * 65536, Ah, Al, Bh, Bl, lda, ldb, (c + 1) * 64, tid);
            CP_COMMIT();
            CP_WAIT(1);
        } else {
            CP_WAIT(0);
        }
        __syncthreads();
        if (tid < 32) {
            asm volatile("tcgen05.fence::after_thread_sync;" ::: "memory");
            if (elect_one_pred()) {
                asm volatile("fence.proxy.async.shared::cta;" ::: "memory");
                const uint32_t base = BUF + cur * 65536;
                const uint64_t dAh = mk_desc(base);
                const uint64_t dAl = mk_desc(base + 16384);
                const uint64_t dBh = mk_desc(base + 32768);
                const uint64_t dBl = mk_desc(base + 49152);
                mma4(tmem, dAh, dBh, c == 0);
                mma4(tmem, dAl, dBh, false);
                mma4(tmem, dAh, dBl, false);
                asm volatile(
                    "tcgen05.commit.cta_group::1.mbarrier::arrive::one.shared::cluster.b64 [%0];"
                    :: "r"(cur ? MB1 : MB0) : "memory");
            }
        }
    }

    // --------- epilogue ----------
    mbar_wait(((nc - 1) & 1) ? MB1 : MB0, ((nc - 1) >> 1) & 1);
    asm volatile("tcgen05.fence::after_thread_sync;" ::: "memory");

    const int lid = tid & 31;
    const long rowg = row0 + (tid >> 5) * 32 + lid;

#pragma unroll
    for (int cb = 0; cb < 4; cb++) {
        uint32_t r[32];
        TCG_LD32(r, tmem + cb * 32);
        asm volatile("tcgen05.wait::ld.sync.aligned;" ::: "memory");
        if (split) {
            uint32_t hp[16], lp[16];
#pragma unroll
            for (int j = 0; j < 16; j++) {
                float v0 = __uint_as_float(r[2 * j]);
                float v1 = __uint_as_float(r[2 * j + 1]);
                __nv_bfloat16 h0 = __float2bfloat16(v0);
                __nv_bfloat16 h1 = __float2bfloat16(v1);
                __nv_bfloat16 l0 = __float2bfloat16(v0 - __bfloat162float(h0));
                __nv_bfloat16 l1 = __float2bfloat16(v1 - __bfloat162float(h1));
                hp[j] = (uint32_t)__bfloat16_as_ushort(h0) |
                        ((uint32_t)__bfloat16_as_ushort(h1) << 16);
                lp[j] = (uint32_t)__bfloat16_as_ushort(l0) |
                        ((uint32_t)__bfloat16_as_ushort(l1) << 16);
            }
            uint4* ph = (uint4*)(Ch + rowg * ldc + col0 + cb * 32);
            uint4* pl = (uint4*)(Cl + rowg * ldc + col0 + cb * 32);
#pragma unroll
            for (int q = 0; q < 4; q++) {
                ph[q] = make_uint4(hp[4 * q], hp[4 * q + 1], hp[4 * q + 2], hp[4 * q + 3]);
                pl[q] = make_uint4(lp[4 * q], lp[4 * q + 1], lp[4 * q + 2], lp[4 * q + 3]);
            }
        } else {
            float4* pf = (float4*)(Cf + rowg * ldc + col0 + cb * 32);
#pragma unroll
            for (int q = 0; q < 8; q++) {
                pf[q] = make_float4(__uint_as_float(r[4 * q]),
                                    __uint_as_float(r[4 * q + 1]),
                                    __uint_as_float(r[4 * q + 2]),
                                    __uint_as_float(r[4 * q + 3]));
            }
        }
    }
    __syncthreads();
    if (tid < 32) {
        asm volatile("tcgen05.relinquish_alloc_permit.cta_group::1.sync.aligned;" ::: "memory");
        asm volatile("tcgen05.dealloc.cta_group::1.sync.aligned.b32 %0, %1;"
                     :: "r"(tmem), "r"(128u));
    }
#else
    // portable-pass fallback (never runs on HW; the sm_103a cubin is used)
    (void)MB0; (void)MB1; (void)BUF;
    for (int j = tid; j < 128; j += 128) {
        for (int i = 0; i < 128; i++) {
            float acc = 0.0f;
            for (int k = 0; k < K; k++) {
                float a = __bfloat162float(Ah[(long)i * lda + k]) +
                          __bfloat162float(Al[(long)i * lda + k]);
                float b = __bfloat162float(Bh[(long)j * ldb + k]) +
                          __bfloat162float(Bl[(long)j * ldb + k]);
                acc += a * b;
            }
            long o = (row0 + i) * ldc + col0 + j;
            if (split) {
                __nv_bfloat16 h = __float2bfloat16(acc);
                Ch[o] = h; Cl[o] = __float2bfloat16(acc - __bfloat162float(h));
            } else Cf[o] = acc;
        }
    }
#endif
}

// ------------------------------ prep kernels -------------------------------
__global__ void split_kernel(const float* __restrict__ in,
                             __nv_bfloat16* __restrict__ oh,
                             __nv_bfloat16* __restrict__ ol, long n)
{
    long i = (long)blockIdx.x * blockDim.x + threadIdx.x;
    if (i >= n) return;
    float v = in[i];
    __nv_bfloat16 h = __float2bfloat16(v);
    oh[i] = h;
    ol[i] = __float2bfloat16(v - __bfloat162float(h));
}

__global__ void split_transpose(const float* __restrict__ in,
                                __nv_bfloat16* __restrict__ oh,
                                __nv_bfloat16* __restrict__ ol, int R, int C)
{
    __shared__ float t[32][33];
    const long bs = (long)blockIdx.z * R * C;
    in += bs; oh += bs; ol += bs;
    const int c0 = blockIdx.x * 32, r0 = blockIdx.y * 32;
#pragma unroll
    for (int rr = threadIdx.y; rr < 32; rr += 8)
        t[rr][threadIdx.x] = in[(long)(r0 + rr) * C + c0 + threadIdx.x];
    __syncthreads();
#pragma unroll
    for (int cc = threadIdx.y; cc < 32; cc += 8) {
        float v = t[threadIdx.x][cc];
        __nv_bfloat16 h = __float2bfloat16(v);
        long o = (long)(c0 + cc) * R + r0 + threadIdx.x;
        oh[o] = h;
        ol[o] = __float2bfloat16(v - __bfloat162float(h));
    }
}

__global__ void pair_transpose(const __nv_bfloat16* __restrict__ ih,
                               const __nv_bfloat16* __restrict__ il,
                               __nv_bfloat16* __restrict__ oh,
                               __nv_bfloat16* __restrict__ ol, int R, int C)
{
    __shared__ __nv_bfloat16 th[32][33];
    __shared__ __nv_bfloat16 tl[32][33];
    const long bs = (long)blockIdx.z * R * C;
    ih += bs; il += bs; oh += bs; ol += bs;
    const int c0 = blockIdx.x * 32, r0 = blockIdx.y * 32;
#pragma unroll
    for (int rr = threadIdx.y; rr < 32; rr += 8) {
        long idx = (long)(r0 + rr) * C + c0 + threadIdx.x;
        th[rr][threadIdx.x] = ih[idx];
        tl[rr][threadIdx.x] = il[idx];
    }
    __syncthreads();
#pragma unroll
    for (int cc = threadIdx.y; cc < 32; cc += 8) {
        long o = (long)(c0 + cc) * R + r0 + threadIdx.x;
        oh[o] = th[threadIdx.x][cc];
        ol[o] = tl[threadIdx.x][cc];
    }
}

__global__ void colsoftmax_tc()
{
    const int z = blockIdx.y;
    const int j = blockIdx.x * blockDim.x + threadIdx.x;
    const float* S = g_S + (long)z * 1048576;
    __nv_bfloat16* Ph = g_Phi + (long)z * 1048576;
    __nv_bfloat16* Pl = g_Plo + (long)z * 1048576;
    const float scale = 0.03125f;

    float m = -3.402823e38f;
#pragma unroll 8
    for (int i = 0; i < 1024; ++i) m = fmaxf(m, S[i * 1024 + j]);
    const float mm = m * scale;

    float s = 0.0f;
    for (int i = 0; i < 1024; ++i) {
        float t = S[i * 1024 + j] * scale - mm;
        s += (t > -25.0f) ? __expf(t) : 0.0f;
    }
    const float inv = 1.0f / s;

    for (int i = 0; i < 1024; ++i) {
        float t = S[i * 1024 + j] * scale - mm;
        float p = ((t > -25.0f) ? __expf(t) : 0.0f) * inv;
        __nv_bfloat16 h = __float2bfloat16(p);
        Ph[i * 1024 + j] = h;
        Pl[i * 1024 + j] = __float2bfloat16(p - __bfloat162float(h));
    }
}

// -------- check: did the TC path produce real (nonzero) V? -----------------
__global__ void check_kernel()
{
    __shared__ float red[256];
    float a = 0.0f;
    for (long i = threadIdx.x; i < 65536; i += 256)
        a += fabsf(__bfloat162float(g_Vhi[i * 1151]));   // strided sample
    red[threadIdx.x] = a;
    __syncthreads();
    for (int st = 128; st > 0; st >>= 1) {
        if (threadIdx.x < st) red[threadIdx.x] += red[threadIdx.x + st];
        __syncthreads();
    }
    if (threadIdx.x == 0) g_ok = (red[0] > 0.0f) ? 1 : 0;
}

// ===================== SIMT fp32 fallback (proven, round 1) ================
#define BM 128
#define BN 128
#define BK 8

__global__ __launch_bounds__(256, 2)
void simt_gemm(int mode,
               const float* __restrict__ x,
               const float* __restrict__ WQ,
               const float* __restrict__ WK,
               const float* __restrict__ WV,
               const float* __restrict__ WO,
               float* __restrict__ out)
{
    if (g_ok) return;   // TC path valid -> no-op

    const float* A;
    const float* B;
    float* C;
    int lda, ldb, ldc, K;
    const int z = blockIdx.z;

    if (mode == 0) {
        int which = z / 12;
        int h = z - which * 12;
        A = x;  lda = 768;  K = 768;
        const float* Wb = (which == 0) ? WQ : (which == 1) ? WK : WV;
        B = Wb + h * 589824;  ldb = 768;
        float* Ob = (which == 0) ? g_Qf : (which == 1) ? g_Kf : g_Vf;
        C = Ob + h * 6291456; ldc = 768;
    } else if (mode == 1) {
        A = g_Qf + z * 786432; lda = 768;  K = 768;
        B = g_Kf + z * 786432; ldb = 1024;
        C = g_S + (long)z * 1048576; ldc = 1024;
    } else if (mode == 2) {
        int h = z >> 3, b = z & 7;
        A = g_S + (long)z * 1048576; lda = 1024; K = 1024;
        B = g_Vf + z * 786432;  ldb = 768;
        C = g_Zf + b * 9437184 + h * 786432; ldc = 768;
    } else {
        A = g_Zf; lda = 9216; K = 9216;
        B = WO;  ldb = 768;
        C = out; ldc = 768;
    }

    __shared__ float As[2][BK][BM];
    __shared__ float Bs[2][BK][BN];

    const int tid  = threadIdx.x;
    const int row0 = blockIdx.y * BM;
    const int col0 = blockIdx.x * BN;

    const int arow = tid >> 1;
    const int acol = (tid & 1) << 2;
    const int brow = tid >> 5;
    const int bcol = (tid & 31) << 2;

    const float* Aptr = A + (long)(row0 + arow) * lda + acol;
    const float* Bptr = B + (long)brow * ldb + col0 + bcol;

    const int rowb = (tid >> 4) << 3;
    const int colb = (tid & 15) << 3;

    float acc[8][8];
#pragma unroll
    for (int i = 0; i < 8; i++)
#pragma unroll
        for (int j = 0; j < 8; j++) acc[i][j] = 0.0f;

    float4 a4 = *(const float4*)(Aptr);
    float4 b4 = *(const float4*)(Bptr);
    As[0][acol + 0][arow] = a4.x;
    As[0][acol + 1][arow] = a4.y;
    As[0][acol + 2][arow] = a4.z;
    As[0][acol + 3][arow] = a4.w;
    *(float4*)&Bs[0][brow][bcol] = b4;
    __syncthreads();

    const int nIter = K / BK;
    for (int it = 0; it < nIter; ++it) {
        const int cur = it & 1;
        const bool more = (it + 1) < nIter;
        if (more) {
            a4 = *(const float4*)(Aptr + (it + 1) * BK);
            b4 = *(const float4*)(Bptr + (long)(it + 1) * BK * ldb);
        }
#pragma unroll
        for (int kk = 0; kk < BK; ++kk) {
            float ar[8], br[8];
            *(float4*)&ar[0] = *(const float4*)&As[cur][kk][rowb];
            *(float4*)&ar[4] = *(const float4*)&As[cur][kk][rowb + 4];
            *(float4*)&br[0] = *(const float4*)&Bs[cur][kk][colb];
            *(float4*)&br[4] = *(const float4*)&Bs[cur][kk][colb + 4];
#pragma unroll
            for (int i = 0; i < 8; i++)
#pragma unroll
                for (int j = 0; j < 8; j++)
                    acc[i][j] += ar[i] * br[j];
        }
        if (more) {
            const int nxt = cur ^ 1;
            As[nxt][acol + 0][arow] = a4.x;
            As[nxt][acol + 1][arow] = a4.y;
            As[nxt][acol + 2][arow] = a4.z;
            As[nxt][acol + 3][arow] = a4.w;
            *(float4*)&Bs[nxt][brow][bcol] = b4;
        }
        __syncthreads();
    }

#pragma unroll
    for (int i = 0; i < 8; i++) {
        float* Cp = C + (long)(row0 + rowb + i) * ldc + col0 + colb;
        *(float4*)(Cp)     = make_float4(acc[i][0], acc[i][1], acc[i][2], acc[i][3]);
        *(float4*)(Cp + 4) = make_float4(acc[i][4], acc[i][5], acc[i][6], acc[i][7]);
    }
}

__global__ void simt_softmax()
{
    if (g_ok) return;
    const int z = blockIdx.y;
    const int j = blockIdx.x * blockDim.x + threadIdx.x;
    float* S = g_S + (long)z * 1048576;
    const float scale = 0.03125f;

    float m = -3.402823e38f;
#pragma unroll 8
    for (int i = 0; i < 1024; ++i) m = fmaxf(m, S[i * 1024 + j]);
    const float mm = m * scale;

    float s = 0.0f;
#pragma unroll 8
    for (int i = 0; i < 1024; ++i) s += expf(S[i * 1024 + j] * scale - mm);
    const float inv = 1.0f / s;

#pragma unroll 8
    for (int i = 0; i < 1024; ++i)
        S[i * 1024 + j] = expf(S[i * 1024 + j] * scale - mm) * inv;
}

// --------------------------------- launch ----------------------------------
extern "C" void kernel_launch(void* const* d_in, const int* in_sizes, int n_in,
                              void* d_out, int out_size)
{
    const float* x  = (const float*)d_in[0];
    const float* WQ = (const float*)d_in[1];
    const float* WK = (const float*)d_in[2];
    const float* WV = (const float*)d_in[3];
    const float* WO = (const float*)d_in[4];
    float* out = (float*)d_out;

    const int SMEM = 2048 + 2 * 65536;
    cudaFuncSetAttribute(tc_gemm, cudaFuncAttributeMaxDynamicSharedMemorySize, SMEM);

    // ---------- TC path ----------
    {
        long n = 8192L * 768;
        split_kernel<<<(int)((n + 255) / 256), 256>>>(x, g_xhi, g_xlo, n);
    }
    dim3 tb(32, 8);
    split_transpose<<<dim3(24, 24, 12), tb>>>(WQ, g_WQth, g_WQtl, 768, 768);
    split_transpose<<<dim3(24, 24, 12), tb>>>(WK, g_WKth, g_WKtl, 768, 768);
    split_transpose<<<dim3(24, 24, 12), tb>>>(WV, g_WVth, g_WVtl, 768, 768);
    split_transpose<<<dim3(24, 288, 1), tb>>>(WO, g_WOth, g_WOtl, 9216, 768);

    tc_gemm<<<dim3(6, 64, 36), 128, SMEM>>>(0, out);
    check_kernel<<<1, 256>>>();

    pair_transpose<<<dim3(32, 24, 96), tb>>>(g_Khi, g_Klo, g_Kthi, g_Ktlo, 768, 1024);
    pair_transpose<<<dim3(24, 32, 96), tb>>>(g_Vhi, g_Vlo, g_Vthi, g_Vtlo, 1024, 768);

    tc_gemm<<<dim3(8, 8, 96), 128, SMEM>>>(1, out);
    colsoftmax_tc<<<dim3(4, 96), 256>>>();
    tc_gemm<<<dim3(6, 8, 96), 128, SMEM>>>(2, out);
    tc_gemm<<<dim3(6, 64, 1), 128, SMEM>>>(3, out);

    // ---------- guarded SIMT fallback (no-op when g_ok==1) ----------
    simt_gemm<<<dim3(6, 64, 36), 256>>>(0, x, WQ, WK, WV, WO, out);
    simt_gemm<<<dim3(8, 8, 96), 256>>>(1, x, WQ, WK, WV, WO, out);
    simt_softmax<<<dim3(4, 96), 256>>>();
    simt_gemm<<<dim3(6, 8, 96), 256>>>(2, x, WQ, WK, WV, WO, out);
    simt_gemm<<<dim3(6, 64, 1), 256>>>(3, x, WQ, WK, WV, WO, out);
}